// round 2
// baseline (speedup 1.0000x reference)
#include <cuda_runtime.h>

#define M_ROWS 65536
#define T_LEN  16384
#define RC     128
#define NLAYERS 20

// ---------------- device scratch (no runtime allocation allowed) ----------
__device__ float g_res0[(size_t)M_ROWS * RC];
__device__ float g_res1[(size_t)M_ROWS * RC];
__device__ float g_skipacc[(size_t)M_ROWS * RC];

static const int H_DIL[NLAYERS] = {1,2,4,8,16,32,64,128,256,512,
                                   1,2,4,8,16,32,64,128,256,512};

// ---------------- helpers --------------------------------------------------
__device__ __forceinline__ float fast_tanhf(float x) {
    float ax = fabsf(x);
    float e  = __expf(-2.0f * ax);                 // in (0,1], never overflows
    float r  = __fdividef(1.0f - e, 1.0f + e);     // denom in [1,2]
    return copysignf(r, x);
}
__device__ __forceinline__ float fast_sigmoidf(float x) {
    return 0.5f * fast_tanhf(0.5f * x) + 0.5f;
}
__device__ __forceinline__ void fma4(float4& acc, float a, const float4& w) {
    acc.x += a * w.x; acc.y += a * w.y; acc.z += a * w.z; acc.w += a * w.w;
}
__device__ __forceinline__ float comp(const float4& v, int j) {
    return j == 0 ? v.x : j == 1 ? v.y : j == 2 ? v.z : v.w;
}
__device__ __forceinline__ float4 add4(float4 a, const float4& b) {
    a.x += b.x; a.y += b.y; a.z += b.z; a.w += b.w; return a;
}

// ---------------- init causal conv: k=32, 64ch -> 128ch --------------------
// y[t] = sum_{tap=0}^{31} X[t-31+tap] @ W[tap] + b
// smem: As[96 rows x 64ch] (24.5KB) + Ws[64k x 128n] (32KB) = 57344 B
__global__ __launch_bounds__(256, 2)
void k_init(const float* __restrict__ X, const float* __restrict__ W,
            const float* __restrict__ b, float* __restrict__ res)
{
    extern __shared__ float sm[];
    float4* As4 = (float4*)sm;                 // [row(95)][16 f4]
    float4* Ws4 = (float4*)(sm + 96 * 64);     // [64][32 f4]
    const int tid = threadIdx.x;
    const int tx = tid & 31, ty = tid >> 5;
    const int n0 = tx * 4, m0 = ty * 8;
    const int t0 = blockIdx.x * 64;
    const int bstart = t0 & ~(T_LEN - 1);

    const float4* X4 = (const float4*)X;
    #pragma unroll
    for (int i = 0; i < 6; i++) {
        int idx = tid + i * 256;
        if (idx < 95 * 16) {
            int j = idx >> 4, c4 = idx & 15;
            int g = t0 - 31 + j;
            float4 v = make_float4(0.f, 0.f, 0.f, 0.f);
            if (g >= bstart) v = X4[(size_t)g * 16 + c4];
            As4[j * 16 + c4] = v;
        }
    }

    float4 acc[8];
    float4 bias = *(const float4*)&b[n0];
    #pragma unroll
    for (int r = 0; r < 8; r++) acc[r] = bias;

    const float4* W4 = (const float4*)W;
    for (int tap = 0; tap < 32; tap++) {
        __syncthreads();
        #pragma unroll
        for (int i = 0; i < 8; i++) {
            int idx = tid + i * 256;               // 0..2047 f4
            int kl = idx >> 5, n4 = idx & 31;
            Ws4[kl * 32 + n4] = W4[(size_t)((tap << 6) + kl) * 32 + n4];
        }
        __syncthreads();
        #pragma unroll
        for (int kk4 = 0; kk4 < 16; kk4++) {
            float4 a[8];
            #pragma unroll
            for (int r = 0; r < 8; r++) a[r] = As4[(m0 + r + tap) * 16 + kk4];
            #pragma unroll
            for (int j = 0; j < 4; j++) {
                float4 w = Ws4[(kk4 * 4 + j) * 32 + tx];
                #pragma unroll
                for (int r = 0; r < 8; r++) fma4(acc[r], comp(a[r], j), w);
            }
        }
    }
    #pragma unroll
    for (int r = 0; r < 8; r++)
        *(float4*)&res[(size_t)(t0 + m0 + r) * RC + n0] = acc[r];
}

// ---------------- fused gated dilated layer --------------------------------
// p   = tanh(A@Wf + fb) * sigmoid(A@Wg + gb),  A = [x(t-d) | x(t)]  (K=256)
// out += p@Ws + sb ;  res_out = res_in + p@Wr + rb
// smem: As[64x256] (64KB, aliased by Ps[64x128] in phase 2) + 2x[32x128] W (32KB)
__global__ __launch_bounds__(256, 2)
void k_layer(const float* __restrict__ rin, float* __restrict__ rout,
             const float* __restrict__ fW, const float* __restrict__ fB,
             const float* __restrict__ gW, const float* __restrict__ gB,
             const float* __restrict__ sW, const float* __restrict__ sB,
             const float* __restrict__ rW, const float* __restrict__ rB,
             float* __restrict__ oacc_g, int d, int first)
{
    extern __shared__ float sm[];
    float4* As4 = (float4*)sm;                 // [m(64)][64 f4]  (k-major inside row)
    float4* Wa4 = (float4*)(sm + 64 * 256);    // 32x32 f4
    float4* Wb4 = Wa4 + 32 * 32;
    const int tid = threadIdx.x;
    const int tx = tid & 31, ty = tid >> 5;
    const int n0 = tx * 4, m0 = ty * 8;
    const int t0 = blockIdx.x * 64;

    // ---- load A tile: k<128 -> x(t-d), k>=128 -> x(t) ----
    #pragma unroll
    for (int i = 0; i < 16; i++) {
        int idx = tid + i * 256;                   // 0..4095 f4
        int m = idx >> 6, c4 = idx & 63;
        int tm = t0 + m;
        float4 v = make_float4(0.f, 0.f, 0.f, 0.f);
        if (c4 < 32) {
            if ((tm & (T_LEN - 1)) >= d)
                v = *(const float4*)&rin[(size_t)(tm - d) * RC + c4 * 4];
        } else {
            v = *(const float4*)&rin[(size_t)tm * RC + (c4 - 32) * 4];
        }
        As4[m * 64 + c4] = v;
    }

    float4 fa[8], ga[8];
    {
        float4 fb4 = *(const float4*)&fB[n0];
        float4 gb4 = *(const float4*)&gB[n0];
        #pragma unroll
        for (int r = 0; r < 8; r++) { fa[r] = fb4; ga[r] = gb4; }
    }

    // ---- phase 1: f/g GEMMs over K=256, weight chunks of 32 ----
    const float4* fW4 = (const float4*)fW;
    const float4* gW4 = (const float4*)gW;
    for (int c = 0; c < 8; c++) {
        __syncthreads();
        #pragma unroll
        for (int i = 0; i < 8; i++) {
            int idx = tid + i * 256;               // 0..2047
            int sel = idx >> 10, e = idx & 1023;
            int kl = e >> 5, n4 = e & 31;
            const float4* src = sel ? gW4 : fW4;
            float4 v = src[(size_t)(c * 32 + kl) * 32 + n4];
            (sel ? Wb4 : Wa4)[kl * 32 + n4] = v;
        }
        __syncthreads();
        #pragma unroll
        for (int kk4 = 0; kk4 < 8; kk4++) {
            float4 a[8];
            #pragma unroll
            for (int r = 0; r < 8; r++) a[r] = As4[(m0 + r) * 64 + c * 8 + kk4];
            #pragma unroll
            for (int j = 0; j < 4; j++) {
                float4 wf = Wa4[(kk4 * 4 + j) * 32 + tx];
                float4 wg = Wb4[(kk4 * 4 + j) * 32 + tx];
                #pragma unroll
                for (int r = 0; r < 8; r++) {
                    float av = comp(a[r], j);
                    fma4(fa[r], av, wf);
                    fma4(ga[r], av, wg);
                }
            }
        }
    }
    __syncthreads();   // everyone done reading As before we alias it with Ps

    // ---- activations; write p into Ps (aliases As) ----
    float4* Ps4 = (float4*)sm;                 // [m(64)][32 f4]
    #pragma unroll
    for (int r = 0; r < 8; r++) {
        float4 p;
        p.x = fast_tanhf(fa[r].x) * fast_sigmoidf(ga[r].x);
        p.y = fast_tanhf(fa[r].y) * fast_sigmoidf(ga[r].y);
        p.z = fast_tanhf(fa[r].z) * fast_sigmoidf(ga[r].z);
        p.w = fast_tanhf(fa[r].w) * fast_sigmoidf(ga[r].w);
        Ps4[(m0 + r) * 32 + tx] = p;
    }

    // ---- phase 2: skip/res GEMMs over K=128 ----
    {
        float4 sb4 = *(const float4*)&sB[n0];
        float4 rb4 = *(const float4*)&rB[n0];
        #pragma unroll
        for (int r = 0; r < 8; r++) { fa[r] = sb4; ga[r] = rb4; }
    }
    const float4* sW4 = (const float4*)sW;
    const float4* rW4 = (const float4*)rW;
    for (int c = 0; c < 4; c++) {
        __syncthreads();                        // also orders Ps writes -> reads
        #pragma unroll
        for (int i = 0; i < 8; i++) {
            int idx = tid + i * 256;
            int sel = idx >> 10, e = idx & 1023;
            int kl = e >> 5, n4 = e & 31;
            const float4* src = sel ? rW4 : sW4;
            float4 v = src[(size_t)(c * 32 + kl) * 32 + n4];
            (sel ? Wb4 : Wa4)[kl * 32 + n4] = v;
        }
        __syncthreads();
        #pragma unroll
        for (int kk4 = 0; kk4 < 8; kk4++) {
            float4 a[8];
            #pragma unroll
            for (int r = 0; r < 8; r++) a[r] = Ps4[(m0 + r) * 32 + c * 8 + kk4];
            #pragma unroll
            for (int j = 0; j < 4; j++) {
                float4 ws = Wa4[(kk4 * 4 + j) * 32 + tx];
                float4 wr = Wb4[(kk4 * 4 + j) * 32 + tx];
                #pragma unroll
                for (int r = 0; r < 8; r++) {
                    float av = comp(a[r], j);
                    fma4(fa[r], av, ws);
                    fma4(ga[r], av, wr);
                }
            }
        }
    }

    // ---- epilogue: res_out = res_in + racc ; out (+)= oacc ----
    #pragma unroll
    for (int r = 0; r < 8; r++) {
        size_t gidx = (size_t)(t0 + m0 + r) * RC + n0;
        float4 ro = *(const float4*)&rin[gidx];
        *(float4*)&rout[gidx] = add4(ga[r], ro);
        float4 ov = fa[r];
        if (!first) ov = add4(ov, *(const float4*)&oacc_g[gidx]);
        *(float4*)&oacc_g[gidx] = ov;
    }
}

// ---------------- fused skip stack ------------------------------------------
// h = relu(out)@W0+b0 ; 31x: h = relu(h)@Wr[i]+br[i] ; y = relu(h)@Wf+bf
// all weights resident in smem (45312 floats = 177KB); thread-per-row.
#define SK_W0   0
#define SK_WR   4096
#define SK_WF   35840
#define SK_B0   44032
#define SK_BR   44064
#define SK_BF   45056
#define SK_TOT  45312

__global__ __launch_bounds__(512)
void k_skip(const float* __restrict__ oacc,
            const float* __restrict__ w0, const float* __restrict__ b0,
            const float* __restrict__ wr, const float* __restrict__ br,
            const float* __restrict__ wf, const float* __restrict__ bf,
            float* __restrict__ y)
{
    extern __shared__ float sm[];
    const int tid = threadIdx.x;
    for (int i = tid; i < 4096;  i += 512) sm[SK_W0 + i] = w0[i];
    for (int i = tid; i < 31744; i += 512) sm[SK_WR + i] = wr[i];
    for (int i = tid; i < 8192;  i += 512) sm[SK_WF + i] = wf[i];
    for (int i = tid; i < 32;    i += 512) sm[SK_B0 + i] = b0[i];
    for (int i = tid; i < 992;   i += 512) sm[SK_BR + i] = br[i];
    for (int i = tid; i < 256;   i += 512) sm[SK_BF + i] = bf[i];
    __syncthreads();

    const int row = blockIdx.x * 512 + tid;

    float h[32];
    #pragma unroll
    for (int c = 0; c < 32; c++) h[c] = sm[SK_B0 + c];

    // stage 1: 128 -> 32
    const float4* in4 = (const float4*)(oacc + (size_t)row * RC);
    const float4* w0_4 = (const float4*)(sm + SK_W0);
    #pragma unroll 4
    for (int k4 = 0; k4 < 32; k4++) {
        float4 x = __ldg(&in4[k4]);
        x.x = fmaxf(x.x, 0.f); x.y = fmaxf(x.y, 0.f);
        x.z = fmaxf(x.z, 0.f); x.w = fmaxf(x.w, 0.f);
        #pragma unroll
        for (int j = 0; j < 4; j++) {
            float xv = comp(x, j);
            #pragma unroll
            for (int c4 = 0; c4 < 8; c4++) {
                float4 w = w0_4[(k4 * 4 + j) * 8 + c4];
                h[c4*4+0] += xv * w.x; h[c4*4+1] += xv * w.y;
                h[c4*4+2] += xv * w.z; h[c4*4+3] += xv * w.w;
            }
        }
    }

    // stage 2: 31x (32 -> 32)
    #pragma unroll 1
    for (int step = 0; step < 31; step++) {
        float hn[32];
        #pragma unroll
        for (int c = 0; c < 32; c++) hn[c] = sm[SK_BR + step * 32 + c];
        const float4* wr4 = (const float4*)(sm + SK_WR + step * 1024);
        #pragma unroll
        for (int k = 0; k < 32; k++) {
            float xv = fmaxf(h[k], 0.f);
            #pragma unroll
            for (int c4 = 0; c4 < 8; c4++) {
                float4 w = wr4[k * 8 + c4];
                hn[c4*4+0] += xv * w.x; hn[c4*4+1] += xv * w.y;
                hn[c4*4+2] += xv * w.z; hn[c4*4+3] += xv * w.w;
            }
        }
        #pragma unroll
        for (int c = 0; c < 32; c++) h[c] = hn[c];
    }

    // stage 3: 32 -> 256
    float rh[32];
    #pragma unroll
    for (int k = 0; k < 32; k++) rh[k] = fmaxf(h[k], 0.f);
    const float4* wf4 = (const float4*)(sm + SK_WF);
    const float4* bf4 = (const float4*)(sm + SK_BF);
    float* yrow = y + (size_t)row * 256;
    #pragma unroll 1
    for (int g = 0; g < 8; g++) {
        float4 acc[8];
        #pragma unroll
        for (int c4 = 0; c4 < 8; c4++) acc[c4] = bf4[g * 8 + c4];
        #pragma unroll
        for (int k = 0; k < 32; k++) {
            float xv = rh[k];
            #pragma unroll
            for (int c4 = 0; c4 < 8; c4++) {
                float4 w = wf4[k * 64 + g * 8 + c4];
                acc[c4].x += xv * w.x; acc[c4].y += xv * w.y;
                acc[c4].z += xv * w.z; acc[c4].w += xv * w.w;
            }
        }
        #pragma unroll
        for (int c4 = 0; c4 < 8; c4++)
            *(float4*)&yrow[g * 32 + c4 * 4] = acc[c4];
    }
}

// ---------------- launch ----------------------------------------------------
extern "C" void kernel_launch(void* const* d_in, const int* in_sizes, int n_in,
                              void* d_out, int out_size)
{
    const float* X      = (const float*)d_in[0];
    const float* init_w = (const float*)d_in[1];
    const float* init_b = (const float*)d_in[2];
    const float* f_w    = (const float*)d_in[3];
    const float* f_b    = (const float*)d_in[4];
    const float* g_w    = (const float*)d_in[5];
    const float* g_b    = (const float*)d_in[6];
    const float* skip_w = (const float*)d_in[7];
    const float* skip_b = (const float*)d_in[8];
    const float* res_w  = (const float*)d_in[9];
    const float* res_b  = (const float*)d_in[10];
    const float* sk0_w  = (const float*)d_in[11];
    const float* sk0_b  = (const float*)d_in[12];
    const float* skr_w  = (const float*)d_in[13];
    const float* skr_b  = (const float*)d_in[14];
    const float* fin_w  = (const float*)d_in[15];
    const float* fin_b  = (const float*)d_in[16];

    float *r0, *r1, *oa;
    cudaGetSymbolAddress((void**)&r0, g_res0);
    cudaGetSymbolAddress((void**)&r1, g_res1);
    cudaGetSymbolAddress((void**)&oa, g_skipacc);

    const int SM_INIT  = 96 * 64 * 4 + 64 * 128 * 4;        // 57344
    const int SM_LAYER = 64 * 256 * 4 + 2 * 32 * 128 * 4;   // 98304
    const int SM_SKIP  = SK_TOT * 4;                        // 181248

    cudaFuncSetAttribute(k_init,  cudaFuncAttributeMaxDynamicSharedMemorySize, SM_INIT);
    cudaFuncSetAttribute(k_layer, cudaFuncAttributeMaxDynamicSharedMemorySize, SM_LAYER);
    cudaFuncSetAttribute(k_skip,  cudaFuncAttributeMaxDynamicSharedMemorySize, SM_SKIP);

    k_init<<<M_ROWS / 64, 256, SM_INIT>>>(X, init_w, init_b, r0);

    const float* rin = r0;
    float* rout = r1;
    for (int i = 0; i < NLAYERS; i++) {
        k_layer<<<M_ROWS / 64, 256, SM_LAYER>>>(
            rin, rout,
            f_w    + (size_t)i * 2 * RC * RC, f_b    + (size_t)i * RC,
            g_w    + (size_t)i * 2 * RC * RC, g_b    + (size_t)i * RC,
            skip_w + (size_t)i * RC * RC,     skip_b + (size_t)i * RC,
            res_w  + (size_t)i * RC * RC,     res_b  + (size_t)i * RC,
            oa, H_DIL[i], (i == 0) ? 1 : 0);
        const float* t = rin; rin = rout; rout = (float*)t;
    }

    k_skip<<<M_ROWS / 512, 512, SM_SKIP>>>(oa, sk0_w, sk0_b, skr_w, skr_b,
                                           fin_w, fin_b, (float*)d_out);
}